// round 13
// baseline (speedup 1.0000x reference)
#include <cuda_runtime.h>
#include <cuda_bf16.h>
#include <cstdint>

// MXFP8 e4m3 block-32 quantize->dequantize.
// Persistent grid-stride kernel: fixed grid (~8 CTAs/SM), each thread loops
// over pairs of float4 tiles with a 1-deep software pipeline — next
// iteration's two LDG.128s are issued before the current pair's shuffle/
// quantize/store work, so memory latency overlaps compute continuously
// without front-batching more than 2 loads (keeps cross-CTA L1tex-queue
// spread at the floor) and without one-shot CTA wave churn.
// 8 consecutive threads own one 32-elem block; amax via 3 butterfly shuffles.
// All scale math is exact powers of two via exponent bits (bit-exact vs ref).

__device__ __forceinline__ float blk_scale(float m, float& inv_scale) {
    // shared_exp = floor(log2(amax)) - 8, clamped at -127.
    unsigned mb = __float_as_uint(m);
    int ef = (int)(mb >> 23);
    int se = (ef == 0) ? -127 : (ef - 127 - 8);
    se = max(se, -127);
    inv_scale = __uint_as_float((unsigned)(127 - se) << 23);
    return (se >= -126) ? __uint_as_float((unsigned)(se + 127) << 23)
                        : __uint_as_float(0x00400000u);   // 2^-127 denormal
}

__device__ __forceinline__ float q1(float a, float inv_scale, float scale) {
    float as = fabsf(a) * inv_scale;           // exact: power-of-two multiply
    unsigned b = __float_as_uint(as);
    int pe = (int)(b >> 23) - 127;             // denormal 'as' -> very negative
    pe = max(pe, -6);                          // MIN_EXP clamp (covers denorms)
    float lsh = __uint_as_float((unsigned)(3 - pe + 127) << 23);   // 2^(3-pe)
    float ils = __uint_as_float((unsigned)(pe - 3 + 127) << 23);   // 2^(pe-3)
    float q = floorf(as * lsh + 0.5f);         // round half away from zero
    float d = fminf(q * ils, 448.0f);          // saturate e4m3 max norm
    return copysignf(d * scale, a);
}

__device__ __forceinline__ float amax4(float4 v) {
    return fmaxf(fmaxf(fabsf(v.x), fabsf(v.y)), fmaxf(fabsf(v.z), fabsf(v.w)));
}

__device__ __forceinline__ float4 qtile(float4 v, float is, float s) {
    float4 r;
    r.x = q1(v.x, is, s); r.y = q1(v.y, is, s);
    r.z = q1(v.z, is, s); r.w = q1(v.w, is, s);
    return r;
}

// process one loaded pair: reduce, scale, quantize, store
__device__ __forceinline__ void process_pair(float4 v0, float4 v1,
                                             float4* __restrict__ out,
                                             int i0, int i1, int n4) {
    float m0 = amax4(v0), m1 = amax4(v1);
    m0 = fmaxf(m0, __shfl_xor_sync(0xffffffffu, m0, 1));
    m1 = fmaxf(m1, __shfl_xor_sync(0xffffffffu, m1, 1));
    m0 = fmaxf(m0, __shfl_xor_sync(0xffffffffu, m0, 2));
    m1 = fmaxf(m1, __shfl_xor_sync(0xffffffffu, m1, 2));
    m0 = fmaxf(m0, __shfl_xor_sync(0xffffffffu, m0, 4));
    m1 = fmaxf(m1, __shfl_xor_sync(0xffffffffu, m1, 4));
    float is0, is1;
    float s0 = blk_scale(m0, is0);
    float s1 = blk_scale(m1, is1);
    if (i0 < n4) __stcs(out + i0, qtile(v0, is0, s0));
    if (i1 < n4) __stcs(out + i1, qtile(v1, is1, s1));
}

__global__ __launch_bounds__(256) void mxq_kernel(const float4* __restrict__ x,
                                                  float4* __restrict__ out,
                                                  int n4) {
    const int stride = gridDim.x * 512;        // float4s per grid iteration
    int i0 = blockIdx.x * 512 + threadIdx.x;   // tile A index
    // tile B is i0 + 256

    // prologue: load first pair
    float4 v0 = make_float4(0.f, 0.f, 0.f, 0.f), v1 = v0;
    if (i0 < n4)       v0 = __ldcs(x + i0);
    if (i0 + 256 < n4) v1 = __ldcs(x + i0 + 256);

    for (; i0 < n4; ) {
        int ni = i0 + stride;
        // prefetch next pair before touching the current one
        float4 nv0 = make_float4(0.f, 0.f, 0.f, 0.f), nv1 = nv0;
        if (ni < n4)       nv0 = __ldcs(x + ni);
        if (ni + 256 < n4) nv1 = __ldcs(x + ni + 256);

        process_pair(v0, v1, out, i0, i0 + 256, n4);

        v0 = nv0; v1 = nv1;
        i0 = ni;
    }
}

extern "C" void kernel_launch(void* const* d_in, const int* in_sizes, int n_in,
                              void* d_out, int out_size) {
    const float4* x = (const float4*)d_in[0];
    float4* out = (float4*)d_out;
    int n = in_sizes[0];             // 8192*8192, divisible by 4
    int n4 = n >> 2;
    // persistent grid: ~8 CTAs per SM on 152 SMs; never more than needed
    int blocks_needed = (n4 + 511) / 512;
    int blocks = 1216 < blocks_needed ? 1216 : blocks_needed;
    mxq_kernel<<<blocks, 256>>>(x, out, n4);
}

// round 16
// speedup vs baseline: 1.1247x; 1.1247x over previous
#include <cuda_runtime.h>
#include <cuda_bf16.h>
#include <cstdint>

// MXFP8 e4m3 block-32 quantize->dequantize.
// One thread handles TWO float4 tiles (8 elems) from two adjacent 512-thread
// spans -> 2 unconditional back-to-back LDG.128s per thread (MLP_p1=2 keeps
// cross-CTA L1tex-queue spread at the floor). 512-thread CTAs halve the CTA
// count vs the 256-thr variant (13.5 waves instead of 27 at full residency),
// cutting wave-transition overhead. 8 consecutive threads own one 32-element
// block; block amax via 3 butterfly shuffles (xor 1,2,4), two chains
// interleaved. All scale math is exact powers of two via exponent-bit
// manipulation (bit-exact vs the reference).

__device__ __forceinline__ float blk_scale(float m, float& inv_scale) {
    // shared_exp = floor(log2(amax)) - 8, clamped at -127.
    unsigned mb = __float_as_uint(m);
    int ef = (int)(mb >> 23);
    int se = (ef == 0) ? -127 : (ef - 127 - 8);
    se = max(se, -127);
    inv_scale = __uint_as_float((unsigned)(127 - se) << 23);
    return (se >= -126) ? __uint_as_float((unsigned)(se + 127) << 23)
                        : __uint_as_float(0x00400000u);   // 2^-127 denormal
}

__device__ __forceinline__ float q1(float a, float inv_scale, float scale) {
    float as = fabsf(a) * inv_scale;           // exact: power-of-two multiply
    unsigned b = __float_as_uint(as);
    int pe = (int)(b >> 23) - 127;             // denormal 'as' -> very negative
    pe = max(pe, -6);                          // MIN_EXP clamp (covers denorms)
    float lsh = __uint_as_float((unsigned)(3 - pe + 127) << 23);   // 2^(3-pe)
    float ils = __uint_as_float((unsigned)(pe - 3 + 127) << 23);   // 2^(pe-3)
    float q = floorf(as * lsh + 0.5f);         // round half away from zero
    float d = fminf(q * ils, 448.0f);          // saturate e4m3 max norm
    return copysignf(d * scale, a);
}

__device__ __forceinline__ float amax4(float4 v) {
    return fmaxf(fmaxf(fabsf(v.x), fabsf(v.y)), fmaxf(fabsf(v.z), fabsf(v.w)));
}

__device__ __forceinline__ float4 qtile(float4 v, float is, float s) {
    float4 r;
    r.x = q1(v.x, is, s); r.y = q1(v.y, is, s);
    r.z = q1(v.z, is, s); r.w = q1(v.w, is, s);
    return r;
}

__global__ __launch_bounds__(512) void mxq_kernel(const float4* __restrict__ x,
                                                  float4* __restrict__ out,
                                                  int n4) {
    int i0 = blockIdx.x * 1024 + threadIdx.x;  // tile A
    int i1 = i0 + 512;                         // tile B (independent load)

    if (i1 < n4) {
        // fast path: both tiles in range -> unconditional batched loads
        float4 v0 = __ldcs(x + i0);
        float4 v1 = __ldcs(x + i1);

        float m0 = amax4(v0), m1 = amax4(v1);
        m0 = fmaxf(m0, __shfl_xor_sync(0xffffffffu, m0, 1));
        m1 = fmaxf(m1, __shfl_xor_sync(0xffffffffu, m1, 1));
        m0 = fmaxf(m0, __shfl_xor_sync(0xffffffffu, m0, 2));
        m1 = fmaxf(m1, __shfl_xor_sync(0xffffffffu, m1, 2));
        m0 = fmaxf(m0, __shfl_xor_sync(0xffffffffu, m0, 4));
        m1 = fmaxf(m1, __shfl_xor_sync(0xffffffffu, m1, 4));

        float is0, is1;
        float s0 = blk_scale(m0, is0);
        float s1 = blk_scale(m1, is1);

        __stcs(out + i0, qtile(v0, is0, s0));
        __stcs(out + i1, qtile(v1, is1, s1));
    } else {
        // tail path (unused for 8192x8192, kept for generality)
        #pragma unroll
        for (int t = 0; t < 2; t++) {
            int i = i0 + t * 512;
            float4 v = (i < n4) ? __ldcs(x + i) : make_float4(0.f, 0.f, 0.f, 0.f);
            float m = amax4(v);
            m = fmaxf(m, __shfl_xor_sync(0xffffffffu, m, 1));
            m = fmaxf(m, __shfl_xor_sync(0xffffffffu, m, 2));
            m = fmaxf(m, __shfl_xor_sync(0xffffffffu, m, 4));
            float is;
            float s = blk_scale(m, is);
            if (i < n4) __stcs(out + i, qtile(v, is, s));
        }
    }
}

extern "C" void kernel_launch(void* const* d_in, const int* in_sizes, int n_in,
                              void* d_out, int out_size) {
    const float4* x = (const float4*)d_in[0];
    float4* out = (float4*)d_out;
    int n = in_sizes[0];              // 8192*8192, divisible by 4
    int n4 = n >> 2;
    int blocks = (n4 + 1023) / 1024;  // 1024 float4s (two 512-tiles) per block
    mxq_kernel<<<blocks, 512>>>(x, out, n4);
}

// round 17
// speedup vs baseline: 1.1301x; 1.0048x over previous
#include <cuda_runtime.h>
#include <cuda_bf16.h>
#include <cstdint>

// MXFP8 e4m3 block-32 quantize->dequantize.
// One thread handles TWO float4 tiles (8 elems) from two adjacent 1024-thread
// spans -> 2 unconditional back-to-back LDG.128s per thread (MLP_p1=2 keeps
// cross-CTA L1tex-queue spread at the floor). 1024-thread CTAs (8192 total,
// 2 CTAs/SM = full 2048-thread residency at 32 regs) minimize CTA scheduling
// churn vs the 256/512-thread variants. 8 consecutive threads own one
// 32-element block; block amax via 3 butterfly shuffles (xor 1,2,4), two
// chains interleaved. All scale math is exact powers of two via exponent-bit
// manipulation (bit-exact vs the reference).

__device__ __forceinline__ float blk_scale(float m, float& inv_scale) {
    // shared_exp = floor(log2(amax)) - 8, clamped at -127.
    unsigned mb = __float_as_uint(m);
    int ef = (int)(mb >> 23);
    int se = (ef == 0) ? -127 : (ef - 127 - 8);
    se = max(se, -127);
    inv_scale = __uint_as_float((unsigned)(127 - se) << 23);
    return (se >= -126) ? __uint_as_float((unsigned)(se + 127) << 23)
                        : __uint_as_float(0x00400000u);   // 2^-127 denormal
}

__device__ __forceinline__ float q1(float a, float inv_scale, float scale) {
    float as = fabsf(a) * inv_scale;           // exact: power-of-two multiply
    unsigned b = __float_as_uint(as);
    int pe = (int)(b >> 23) - 127;             // denormal 'as' -> very negative
    pe = max(pe, -6);                          // MIN_EXP clamp (covers denorms)
    float lsh = __uint_as_float((unsigned)(3 - pe + 127) << 23);   // 2^(3-pe)
    float ils = __uint_as_float((unsigned)(pe - 3 + 127) << 23);   // 2^(pe-3)
    float q = floorf(as * lsh + 0.5f);         // round half away from zero
    float d = fminf(q * ils, 448.0f);          // saturate e4m3 max norm
    return copysignf(d * scale, a);
}

__device__ __forceinline__ float amax4(float4 v) {
    return fmaxf(fmaxf(fabsf(v.x), fabsf(v.y)), fmaxf(fabsf(v.z), fabsf(v.w)));
}

__device__ __forceinline__ float4 qtile(float4 v, float is, float s) {
    float4 r;
    r.x = q1(v.x, is, s); r.y = q1(v.y, is, s);
    r.z = q1(v.z, is, s); r.w = q1(v.w, is, s);
    return r;
}

__global__ __launch_bounds__(1024, 2) void mxq_kernel(const float4* __restrict__ x,
                                                      float4* __restrict__ out,
                                                      int n4) {
    int i0 = blockIdx.x * 2048 + threadIdx.x;  // tile A
    int i1 = i0 + 1024;                        // tile B (independent load)

    if (i1 < n4) {
        // fast path: both tiles in range -> unconditional batched loads
        float4 v0 = __ldcs(x + i0);
        float4 v1 = __ldcs(x + i1);

        float m0 = amax4(v0), m1 = amax4(v1);
        m0 = fmaxf(m0, __shfl_xor_sync(0xffffffffu, m0, 1));
        m1 = fmaxf(m1, __shfl_xor_sync(0xffffffffu, m1, 1));
        m0 = fmaxf(m0, __shfl_xor_sync(0xffffffffu, m0, 2));
        m1 = fmaxf(m1, __shfl_xor_sync(0xffffffffu, m1, 2));
        m0 = fmaxf(m0, __shfl_xor_sync(0xffffffffu, m0, 4));
        m1 = fmaxf(m1, __shfl_xor_sync(0xffffffffu, m1, 4));

        float is0, is1;
        float s0 = blk_scale(m0, is0);
        float s1 = blk_scale(m1, is1);

        __stcs(out + i0, qtile(v0, is0, s0));
        __stcs(out + i1, qtile(v1, is1, s1));
    } else {
        // tail path (unused for 8192x8192, kept for generality)
        #pragma unroll
        for (int t = 0; t < 2; t++) {
            int i = i0 + t * 1024;
            float4 v = (i < n4) ? __ldcs(x + i) : make_float4(0.f, 0.f, 0.f, 0.f);
            float m = amax4(v);
            m = fmaxf(m, __shfl_xor_sync(0xffffffffu, m, 1));
            m = fmaxf(m, __shfl_xor_sync(0xffffffffu, m, 2));
            m = fmaxf(m, __shfl_xor_sync(0xffffffffu, m, 4));
            float is;
            float s = blk_scale(m, is);
            if (i < n4) __stcs(out + i, qtile(v, is, s));
        }
    }
}

extern "C" void kernel_launch(void* const* d_in, const int* in_sizes, int n_in,
                              void* d_out, int out_size) {
    const float4* x = (const float4*)d_in[0];
    float4* out = (float4*)d_out;
    int n = in_sizes[0];              // 8192*8192, divisible by 4
    int n4 = n >> 2;
    int blocks = (n4 + 2047) / 2048;  // 2048 float4s (two 1024-tiles) per block
    mxq_kernel<<<blocks, 1024>>>(x, out, n4);
}